// round 10
// baseline (speedup 1.0000x reference)
#include <cuda_runtime.h>

// out[n, k=9*i+j, h, w] = sum_z A[n,z,h,w] * B[n,z, h+j-4, w+i-4]  (zero pad)
// N=8, Z=128, H=W=160.
//
// CTA tile TW=32 x TH=8. Threads (tx=4, h=8, j=9) = 288; warp == one j.
// Thread: 8 consecutive pixels, one row, 9 i-shifts -> 72 scalar accumulators.
// ZC=4 z-chunks, triple-buffered smem via cp.async.cg (zfill halo), one barrier.
// Row strides AROW=BROW=48 floats (== 16 mod 32 banks): every LDS.128 8-lane
// phase covers two rows on disjoint bank halves -> conflict-free.

#define N_  8
#define Z_  128
#define H_  160
#define W_  160
#define TW  32
#define TH  8
#define ZC  4
#define NCH (Z_ / ZC)     // 32
#define AROW 48
#define BROW 48
#define BRN  16           // TH + 8
#define NT  288

#define ASZ (ZC * TH * AROW)      // floats per A buffer (1536)
#define BSZ (ZC * BRN * BROW)     // floats per B buffer (3072)

__global__ __launch_bounds__(NT, 2)
void corr_kernel(const float* __restrict__ A,
                 const float* __restrict__ B,
                 float* __restrict__ out)
{
    __shared__ float As[3][ZC][TH][AROW];   // 3 * 6 KB
    __shared__ float Bs[3][ZC][BRN][BROW];  // 3 * 12 KB  (54 KB total)

    const int tid = threadIdx.x;
    const int tx = tid & 3;          // w = w0 + 8*tx .. +7
    const int h  = (tid >> 2) & 7;
    const int j  = tid >> 5;         // warp index

    const int w0 = blockIdx.x * TW;
    const int h0 = blockIdx.y * TH;
    const int n  = blockIdx.z;

    const size_t plane = (size_t)H_ * W_;
    const float* Abase = A + (size_t)n * Z_ * plane;
    const float* Bbase = B + (size_t)n * Z_ * plane;

    // ------- fixed fill roles (computed once) -------
    // B: ZC*16*10 = 640 float4/chunk (cols 0..39 used; 40..47 pad untouched)
    unsigned boff[3];
    unsigned bsm[3];
    int      bsz[3];
    bool     bact[3];
    #pragma unroll
    for (int s = 0; s < 3; s++) {
        int idx = tid + s * NT;
        bool act = idx < ZC * BRN * 10;
        int ii = act ? idx : 0;
        int z = ii / 160;
        int rem = ii - z * 160;
        int r = rem / 10;
        int c = rem - r * 10;
        int gh = h0 - 4 + r;
        int gw = w0 - 4 + 4 * c;
        bool v = ((unsigned)gh < H_) && ((unsigned)gw <= (W_ - 4));
        bact[s] = act;
        bsz[s] = v ? 16 : 0;
        boff[s] = v ? (unsigned)(z * plane + gh * W_ + gw) : 0u;
        bsm[s] = (unsigned)__cvta_generic_to_shared(&Bs[0][z][r][4 * c]);
    }
    // A: ZC*8*8 = 256 float4/chunk (tid < 256); cols 0..31 used, pad untouched
    const bool aact = tid < ZC * TH * 8;
    int ai = aact ? tid : 0;
    int az = ai >> 6;
    int ar = (ai >> 3) & 7;
    int ac = ai & 7;
    const unsigned aoff = (unsigned)(az * plane + (h0 + ar) * W_ + w0 + 4 * ac);
    const unsigned asm0 = (unsigned)__cvta_generic_to_shared(&As[0][az][ar][4 * ac]);

    // read-side base pointers (buffer 0)
    const float* aRd0 = &As[0][0][h][8 * tx];
    const float* bRd0 = &Bs[0][0][h + j][8 * tx];

    float acc[9][8];
    #pragma unroll
    for (int i = 0; i < 9; i++)
        #pragma unroll
        for (int p = 0; p < 8; p++)
            acc[i][p] = 0.0f;

    auto issue = [&](int chunk, int buf) {
        const float* bsrc = Bbase + (size_t)chunk * ZC * plane;
        const float* asrc = Abase + (size_t)chunk * ZC * plane;
        const unsigned bo = (unsigned)(buf * (BSZ * 4));
        const unsigned ao = (unsigned)(buf * (ASZ * 4));
        #pragma unroll
        for (int s = 0; s < 3; s++) {
            if (bact[s]) {
                asm volatile("cp.async.cg.shared.global [%0], [%1], 16, %2;"
                             :: "r"(bsm[s] + bo), "l"(bsrc + boff[s]), "r"(bsz[s]));
            }
        }
        if (aact) {
            asm volatile("cp.async.cg.shared.global [%0], [%1], 16, 16;"
                         :: "r"(asm0 + ao), "l"(asrc + aoff));
        }
        asm volatile("cp.async.commit_group;");
    };

    // prologue: 2 chunks in flight
    issue(0, 0);
    issue(1, 1);

    int bufc = 0;   // buffer holding chunk ch
    for (int ch = 0; ch < NCH; ch++) {
        if (ch < NCH - 1) asm volatile("cp.async.wait_group 1;");
        else              asm volatile("cp.async.wait_group 0;");
        __syncthreads();   // chunk ch visible; buffer (ch+2)%3 fully drained

        int nb = bufc + 2; if (nb >= 3) nb -= 3;
        if (ch + 2 < NCH) issue(ch + 2, nb);

        const float* aRd = aRd0 + bufc * ASZ;
        const float* bRd = bRd0 + bufc * BSZ;

        #pragma unroll
        for (int z = 0; z < ZC; z++) {
            const float4 a0 = *(const float4*)(aRd + z * (TH * AROW));
            const float4 a1 = *(const float4*)(aRd + z * (TH * AROW) + 4);
            const float4 b0 = *(const float4*)(bRd + z * (BRN * BROW));
            const float4 b1 = *(const float4*)(bRd + z * (BRN * BROW) + 4);
            const float4 b2 = *(const float4*)(bRd + z * (BRN * BROW) + 8);
            const float4 b3 = *(const float4*)(bRd + z * (BRN * BROW) + 12);

            const float a[8] = {a0.x, a0.y, a0.z, a0.w, a1.x, a1.y, a1.z, a1.w};
            const float b[16] = {b0.x, b0.y, b0.z, b0.w, b1.x, b1.y, b1.z, b1.w,
                                 b2.x, b2.y, b2.z, b2.w, b3.x, b3.y, b3.z, b3.w};

            #pragma unroll
            for (int i = 0; i < 9; i++)
                #pragma unroll
                for (int p = 0; p < 8; p++)
                    acc[i][p] += a[p] * b[p + i];
        }

        bufc = (bufc == 2) ? 0 : bufc + 1;
    }

    // ------- store: 18 x STG.128 -------
    float* ob = out + (((size_t)n * 81 + j) * H_ + (h0 + h)) * W_ + w0 + 8 * tx;
    #pragma unroll
    for (int i = 0; i < 9; i++) {
        *(float4*)(ob + (size_t)(9 * i) * plane) =
            make_float4(acc[i][0], acc[i][1], acc[i][2], acc[i][3]);
        *(float4*)(ob + (size_t)(9 * i) * plane + 4) =
            make_float4(acc[i][4], acc[i][5], acc[i][6], acc[i][7]);
    }
}

extern "C" void kernel_launch(void* const* d_in, const int* in_sizes, int n_in,
                              void* d_out, int out_size)
{
    const float* imgA = (const float*)d_in[0];
    const float* imgB = (const float*)d_in[1];
    float* out = (float*)d_out;

    dim3 grid(W_ / TW, H_ / TH, N_);
    corr_kernel<<<grid, NT>>>(imgA, imgB, out);
}

// round 11
// speedup vs baseline: 1.3210x; 1.3210x over previous
#include <cuda_runtime.h>

// out[n, k=9*i+j, h, w] = sum_z A[n,z,h,w] * B[n,z, h+j-4, w+i-4]  (zero pad)
// N=8, Z=128, H=W=160.
//
// Single kernel, two CTA populations (one launch, 1000 CTAs):
//  Path1 (bid<800):  j=0..7.  Tile 32x8, 8 warps (SMSP-balanced), warp==j,
//                    thread = 8 px x 9 i = 72 acc. ZC=4, triple buffer.
//  Path2 (bid>=800): j=8 only. Tile 32x32, 8 warps, thread = 4 px x 9 i = 36
//                    acc. B row = h+4 (no row halo). ZC=2, double buffer.

#define N_  8
#define Z_  128
#define H_  160
#define W_  160
#define NT  256

// path-1 geometry
#define TW  32
#define TH  8
#define ZC  4
#define NCH (Z_ / ZC)             // 32
#define AROW 36
#define BROW 44
#define BRN  16
#define ASZ (ZC * TH * AROW)      // 1152 floats / buffer
#define BSZ (ZC * BRN * BROW)     // 2816 floats / buffer
#define A1BASE 0                  // 3 buffers: 3456 floats
#define B1BASE 3456               // 3 buffers: 8448 floats -> total 11904

// path-2 geometry
#define T2   32
#define Z2C  2
#define NCH2 (Z_ / Z2C)           // 64
#define A2ROW 32
#define B2ROW 40
#define A2SZ (Z2C * T2 * A2ROW)   // 2048 floats / buffer
#define B2SZ (Z2C * T2 * B2ROW)   // 2560 floats / buffer
#define A2BASE 0                  // 2 buffers: 4096
#define B2BASE 4096               // 2 buffers: 5120 -> total 9216

#define SMEM_FLOATS 11904         // 46.5 KB, shared by both paths

__global__ __launch_bounds__(NT, 2)
void corr_kernel(const float* __restrict__ A,
                 const float* __restrict__ B,
                 float* __restrict__ out)
{
    __shared__ float SM[SMEM_FLOATS];

    const int tid = threadIdx.x;
    const int bid = blockIdx.x;
    const size_t plane = (size_t)H_ * W_;

    if (bid < 800) {
        // ================= PATH 1: j = 0..7 =================
        const int tx  = tid & 3;          // w = w0 + 8*tx .. +7
        const int h   = (tid >> 2) & 7;
        const int j   = tid >> 5;         // warp id == j (0..7)

        const int n  = bid / 100;
        const int r0 = bid - n * 100;
        const int h0 = (r0 / 5) * TH;
        const int w0 = (r0 % 5) * TW;

        const float* Abase = A + (size_t)n * Z_ * plane;
        const float* Bbase = B + (size_t)n * Z_ * plane;

        // fill roles: B 640 f4/chunk (3 slots), A 256 f4 (1/thread)
        unsigned boff[3], bsm[3];
        int bszv[3]; bool bact[3];
        #pragma unroll
        for (int s = 0; s < 3; s++) {
            int idx = tid + s * NT;
            bool act = idx < ZC * BRN * 10;
            int ii = act ? idx : 0;
            int z = ii / 160;
            int rem = ii - z * 160;
            int rr = rem / 10;
            int c = rem - rr * 10;
            int gh = h0 - 4 + rr;
            int gw = w0 - 4 + 4 * c;
            bool v = ((unsigned)gh < H_) && ((unsigned)gw <= (W_ - 4));
            bact[s] = act;
            bszv[s] = v ? 16 : 0;
            boff[s] = v ? (unsigned)(z * plane + gh * W_ + gw) : 0u;
            bsm[s] = (unsigned)__cvta_generic_to_shared(
                         &SM[B1BASE + z * (BRN * BROW) + rr * BROW + 4 * c]);
        }
        const int az = tid >> 6;
        const int ar = (tid >> 3) & 7;
        const int ac = tid & 7;
        const unsigned aoff = (unsigned)(az * plane + (h0 + ar) * W_ + w0 + 4 * ac);
        const unsigned asm0 = (unsigned)__cvta_generic_to_shared(
                                  &SM[A1BASE + az * (TH * AROW) + ar * AROW + 4 * ac]);

        const float* aRd0 = &SM[A1BASE + h * AROW + 8 * tx];
        const float* bRd0 = &SM[B1BASE + (h + j) * BROW + 8 * tx];

        float acc[9][8];
        #pragma unroll
        for (int i = 0; i < 9; i++)
            #pragma unroll
            for (int p = 0; p < 8; p++)
                acc[i][p] = 0.0f;

        auto issue = [&](int chunk, int buf) {
            const float* bsrc = Bbase + (size_t)chunk * ZC * plane;
            const float* asrc = Abase + (size_t)chunk * ZC * plane;
            const unsigned bo = (unsigned)(buf * (BSZ * 4));
            const unsigned ao = (unsigned)(buf * (ASZ * 4));
            #pragma unroll
            for (int s = 0; s < 3; s++) {
                if (bact[s])
                    asm volatile("cp.async.cg.shared.global [%0], [%1], 16, %2;"
                                 :: "r"(bsm[s] + bo), "l"(bsrc + boff[s]), "r"(bszv[s]));
            }
            asm volatile("cp.async.cg.shared.global [%0], [%1], 16, 16;"
                         :: "r"(asm0 + ao), "l"(asrc + aoff));
            asm volatile("cp.async.commit_group;");
        };

        issue(0, 0);
        issue(1, 1);

        int bufc = 0;
        for (int ch = 0; ch < NCH; ch++) {
            if (ch < NCH - 1) asm volatile("cp.async.wait_group 1;");
            else              asm volatile("cp.async.wait_group 0;");
            __syncthreads();

            int nb = bufc + 2; if (nb >= 3) nb -= 3;
            if (ch + 2 < NCH) issue(ch + 2, nb);

            const float* aRd = aRd0 + bufc * ASZ;
            const float* bRd = bRd0 + bufc * BSZ;

            #pragma unroll
            for (int z = 0; z < ZC; z++) {
                const float4 a0 = *(const float4*)(aRd + z * (TH * AROW));
                const float4 a1 = *(const float4*)(aRd + z * (TH * AROW) + 4);
                const float4 b0 = *(const float4*)(bRd + z * (BRN * BROW));
                const float4 b1 = *(const float4*)(bRd + z * (BRN * BROW) + 4);
                const float4 b2 = *(const float4*)(bRd + z * (BRN * BROW) + 8);
                const float4 b3 = *(const float4*)(bRd + z * (BRN * BROW) + 12);

                const float a[8] = {a0.x, a0.y, a0.z, a0.w, a1.x, a1.y, a1.z, a1.w};
                const float b[16] = {b0.x, b0.y, b0.z, b0.w, b1.x, b1.y, b1.z, b1.w,
                                     b2.x, b2.y, b2.z, b2.w, b3.x, b3.y, b3.z, b3.w};

                #pragma unroll
                for (int i = 0; i < 9; i++)
                    #pragma unroll
                    for (int p = 0; p < 8; p++)
                        acc[i][p] += a[p] * b[p + i];
            }

            bufc = (bufc == 2) ? 0 : bufc + 1;
        }

        float* ob = out + (((size_t)n * 81 + j) * H_ + (h0 + h)) * W_ + w0 + 8 * tx;
        #pragma unroll
        for (int i = 0; i < 9; i++) {
            *(float4*)(ob + (size_t)(9 * i) * plane) =
                make_float4(acc[i][0], acc[i][1], acc[i][2], acc[i][3]);
            *(float4*)(ob + (size_t)(9 * i) * plane + 4) =
                make_float4(acc[i][4], acc[i][5], acc[i][6], acc[i][7]);
        }
    } else {
        // ================= PATH 2: j = 8 =================
        const int tx = tid & 7;           // w = w0 + 4*tx .. +3
        const int h  = tid >> 3;          // 0..31

        const int b2 = bid - 800;
        const int n  = b2 / 25;
        const int r0 = b2 - n * 25;
        const int h0 = (r0 / 5) * T2;
        const int w0 = (r0 % 5) * T2;

        const float* Abase = A + (size_t)n * Z_ * plane;
        const float* Bbase = B + (size_t)n * Z_ * plane;

        // fill roles: B 640 f4/chunk (rows gh = h0+r+4), A 512 f4 (2 slots)
        unsigned boff[3], bsm[3];
        int bszv[3]; bool bact[3];
        #pragma unroll
        for (int s = 0; s < 3; s++) {
            int idx = tid + s * NT;
            bool act = idx < Z2C * T2 * 10;
            int ii = act ? idx : 0;
            int z = ii / 320;
            int rem = ii - z * 320;
            int rr = rem / 10;
            int c = rem - rr * 10;
            int gh = h0 + rr + 4;
            int gw = w0 - 4 + 4 * c;
            bool v = (gh < H_) && ((unsigned)gw <= (W_ - 4));
            bact[s] = act;
            bszv[s] = v ? 16 : 0;
            boff[s] = v ? (unsigned)(z * plane + gh * W_ + gw) : 0u;
            bsm[s] = (unsigned)__cvta_generic_to_shared(
                         &SM[B2BASE + z * (T2 * B2ROW) + rr * B2ROW + 4 * c]);
        }
        unsigned aoff2[2], asm2[2];
        #pragma unroll
        for (int s = 0; s < 2; s++) {
            int idx = tid + s * NT;          // < 512 always
            int z = idx >> 8;
            int rem = idx & 255;
            int rr = rem >> 3;
            int c = rem & 7;
            aoff2[s] = (unsigned)(z * plane + (h0 + rr) * W_ + w0 + 4 * c);
            asm2[s] = (unsigned)__cvta_generic_to_shared(
                          &SM[A2BASE + z * (T2 * A2ROW) + rr * A2ROW + 4 * c]);
        }

        const float* aRd0 = &SM[A2BASE + h * A2ROW + 4 * tx];
        const float* bRd0 = &SM[B2BASE + h * B2ROW + 4 * tx];

        float acc[9][4];
        #pragma unroll
        for (int i = 0; i < 9; i++)
            #pragma unroll
            for (int p = 0; p < 4; p++)
                acc[i][p] = 0.0f;

        auto issue2 = [&](int chunk, int buf) {
            const float* bsrc = Bbase + (size_t)chunk * Z2C * plane;
            const float* asrc = Abase + (size_t)chunk * Z2C * plane;
            const unsigned bo = (unsigned)(buf * (B2SZ * 4));
            const unsigned ao = (unsigned)(buf * (A2SZ * 4));
            #pragma unroll
            for (int s = 0; s < 3; s++) {
                if (bact[s])
                    asm volatile("cp.async.cg.shared.global [%0], [%1], 16, %2;"
                                 :: "r"(bsm[s] + bo), "l"(bsrc + boff[s]), "r"(bszv[s]));
            }
            #pragma unroll
            for (int s = 0; s < 2; s++) {
                asm volatile("cp.async.cg.shared.global [%0], [%1], 16, 16;"
                             :: "r"(asm2[s] + ao), "l"(asrc + aoff2[s]));
            }
            asm volatile("cp.async.commit_group;");
        };

        issue2(0, 0);
        issue2(1, 1);

        for (int ch = 0; ch < NCH2; ch++) {
            if (ch < NCH2 - 1) asm volatile("cp.async.wait_group 1;");
            else               asm volatile("cp.async.wait_group 0;");
            __syncthreads();

            const int buf = ch & 1;
            const float* aRd = aRd0 + buf * A2SZ;
            const float* bRd = bRd0 + buf * B2SZ;

            #pragma unroll
            for (int z = 0; z < Z2C; z++) {
                const float4 av = *(const float4*)(aRd + z * (T2 * A2ROW));
                const float4 b0 = *(const float4*)(bRd + z * (T2 * B2ROW));
                const float4 b1 = *(const float4*)(bRd + z * (T2 * B2ROW) + 4);
                const float4 b2 = *(const float4*)(bRd + z * (T2 * B2ROW) + 8);

                const float a[4] = {av.x, av.y, av.z, av.w};
                const float b[12] = {b0.x, b0.y, b0.z, b0.w,
                                     b1.x, b1.y, b1.z, b1.w,
                                     b2.x, b2.y, b2.z, b2.w};

                #pragma unroll
                for (int i = 0; i < 9; i++)
                    #pragma unroll
                    for (int p = 0; p < 4; p++)
                        acc[i][p] += a[p] * b[p + i];
            }
            __syncthreads();

            if (ch + 2 < NCH2) issue2(ch + 2, buf);
        }

        float* ob = out + (((size_t)n * 81 + 8) * H_ + (h0 + h)) * W_ + w0 + 4 * tx;
        #pragma unroll
        for (int i = 0; i < 9; i++)
            *(float4*)(ob + (size_t)(9 * i) * plane) =
                make_float4(acc[i][0], acc[i][1], acc[i][2], acc[i][3]);
    }
}

extern "C" void kernel_launch(void* const* d_in, const int* in_sizes, int n_in,
                              void* d_out, int out_size)
{
    const float* imgA = (const float*)d_in[0];
    const float* imgB = (const float*)d_in[1];
    float* out = (float*)d_out;

    corr_kernel<<<1000, NT>>>(imgA, imgB, out);
}